// round 4
// baseline (speedup 1.0000x reference)
#include <cuda_runtime.h>
#include <cuda_bf16.h>
#include <math.h>

#define N_NODES 20000
#define N_EDGES 640000
#define FEAT    128
#define NRBF    20
#define PI_F    3.14159265358979f
#define CUTOFF  5.0f
#define CHUNK   8

typedef unsigned long long ull;

// ---------------- f32x2 packed-math helpers (Blackwell FFMA2 path) -----------
__device__ __forceinline__ ull pack2(float lo, float hi) {
    ull r; asm("mov.b64 %0, {%1, %2};" : "=l"(r) : "f"(lo), "f"(hi)); return r;
}
__device__ __forceinline__ void unpack2(ull v, float& lo, float& hi) {
    asm("mov.b64 {%0, %1}, %2;" : "=f"(lo), "=f"(hi) : "l"(v));
}
__device__ __forceinline__ ull fma2(ull a, ull b, ull c) {
    ull d; asm("fma.rn.f32x2 %0, %1, %2, %3;" : "=l"(d) : "l"(a), "l"(b), "l"(c)); return d;
}
__device__ __forceinline__ ull mul2(ull a, ull b) {
    ull d; asm("mul.rn.f32x2 %0, %1, %2;" : "=l"(d) : "l"(a), "l"(b)); return d;
}

// ---------------- scratch (static device allocations; no cudaMalloc) ----------
__device__ int   g_count[N_NODES];
__device__ int   g_off[N_NODES + 1];
__device__ int   g_cursor[N_NODES];
__device__ int   g_perm[N_EDGES];
__device__ float g_h[N_NODES * FEAT];          // 10.24 MB
__device__ float g_phi[N_NODES * 3 * FEAT];    // 30.72 MB

// ---------------- counting sort of edges by destination node ------------------
// nbrs is int32 [N_EDGES, 2]: nbrs[2e] = dest node i, nbrs[2e+1] = src node j
__global__ void zero_counts_kernel() {
    int i = blockIdx.x * blockDim.x + threadIdx.x;
    if (i < N_NODES) g_count[i] = 0;
}

__global__ void hist_kernel(const int* __restrict__ nbrs) {
    int e = blockIdx.x * blockDim.x + threadIdx.x;
    if (e < N_EDGES) {
        int i = nbrs[2 * e];
        atomicAdd(&g_count[i], 1);
    }
}

// single-block scan: 1024 threads x strip of 20 -> covers 20480 >= 20000
__global__ void scan_kernel() {
    const int STRIP = 20;
    int t = threadIdx.x;
    int base = t * STRIP;
    int local[STRIP];
    int s = 0;
    #pragma unroll
    for (int u = 0; u < STRIP; ++u) {
        int idx = base + u;
        int c = (idx < N_NODES) ? g_count[idx] : 0;
        local[u] = s;       // exclusive within strip
        s += c;
    }
    __shared__ int sums[1024];
    sums[t] = s;
    __syncthreads();
    for (int off = 1; off < 1024; off <<= 1) {
        int v = (t >= off) ? sums[t - off] : 0;
        __syncthreads();
        sums[t] += v;
        __syncthreads();
    }
    int pre = (t > 0) ? sums[t - 1] : 0;
    #pragma unroll
    for (int u = 0; u < STRIP; ++u) {
        int idx = base + u;
        if (idx < N_NODES) {
            int o = pre + local[u];
            g_off[idx]    = o;
            g_cursor[idx] = o;
        }
    }
    if (t == 1023) g_off[N_NODES] = sums[1023];
}

__global__ void scatter_kernel(const int* __restrict__ nbrs) {
    int e = blockIdx.x * blockDim.x + threadIdx.x;
    if (e < N_EDGES) {
        int i = nbrs[2 * e];
        int pos = atomicAdd(&g_cursor[i], 1);
        g_perm[pos] = e;
    }
}

// ---------------- node-feature GEMMs ------------------------------------------
// h = silu(s @ W1 + b1)   [20000,128] @ [128,128]
__global__ __launch_bounds__(128, 4)
void gemm1_kernel(const float* __restrict__ S, const float* __restrict__ W1,
                  const float* __restrict__ b1) {
    __shared__ float As[16][FEAT];
    int row0 = blockIdx.x * 16;
    int tid = threadIdx.x;
    #pragma unroll
    for (int r = 0; r < 16; ++r)
        As[r][tid] = S[(size_t)(row0 + r) * FEAT + tid];
    __syncthreads();

    float acc[16];
    #pragma unroll
    for (int r = 0; r < 16; ++r) acc[r] = 0.f;

    int c = tid;
    #pragma unroll 4
    for (int k = 0; k < FEAT; ++k) {
        float b = W1[k * FEAT + c];
        #pragma unroll
        for (int r = 0; r < 16; ++r) acc[r] = fmaf(As[r][k], b, acc[r]);
    }
    float bias = b1[c];
    #pragma unroll
    for (int r = 0; r < 16; ++r) {
        float x = acc[r] + bias;
        g_h[(size_t)(row0 + r) * FEAT + c] = x / (1.f + expf(-x));  // silu
    }
}

// phi = h @ W2 + b2   [20000,128] @ [128,384]
__global__ __launch_bounds__(128, 4)
void gemm2_kernel(const float* __restrict__ W2, const float* __restrict__ b2) {
    __shared__ float Hs[16][FEAT];
    int row0 = blockIdx.x * 16;
    int tid = threadIdx.x;
    #pragma unroll
    for (int r = 0; r < 16; ++r)
        Hs[r][tid] = g_h[(size_t)(row0 + r) * FEAT + tid];
    __syncthreads();

    float a0[16], a1[16], a2[16];
    #pragma unroll
    for (int r = 0; r < 16; ++r) { a0[r] = 0.f; a1[r] = 0.f; a2[r] = 0.f; }

    int c = tid;
    #pragma unroll 2
    for (int k = 0; k < FEAT; ++k) {
        const float* wrow = W2 + (size_t)k * 384;
        float b0 = wrow[c];
        float b1v = wrow[128 + c];
        float b2v = wrow[256 + c];
        #pragma unroll
        for (int r = 0; r < 16; ++r) {
            float h = Hs[r][k];
            a0[r] = fmaf(h, b0, a0[r]);
            a1[r] = fmaf(h, b1v, a1[r]);
            a2[r] = fmaf(h, b2v, a2[r]);
        }
    }
    float bb0 = b2[c], bb1 = b2[128 + c], bb2 = b2[256 + c];
    #pragma unroll
    for (int r = 0; r < 16; ++r) {
        float* prow = g_phi + (size_t)(row0 + r) * 384;
        prow[c]       = a0[r] + bb0;
        prow[128 + c] = a1[r] + bb1;
        prow[256 + c] = a2[r] + bb2;
    }
}

// ---------------- per-node message + aggregation (f32x2 packed) ---------------
// One CTA (64 threads) per destination node i.
// Thread t owns feature columns (2t, 2t+1) of each of the 3 splits.
struct EdgeRegs { ull p0, p1, p2; float2 a, b, c; };

__device__ __forceinline__ void load_edge(EdgeRegs& E, int j, int f2,
                                          const float* __restrict__ v_j) {
    const float* prow = g_phi + (size_t)j * 384;
    E.p0 = *(const ull*)(prow + f2);
    E.p1 = *(const ull*)(prow + 128 + f2);
    E.p2 = *(const ull*)(prow + 256 + f2);
    const float2* vrow = (const float2*)(v_j + (size_t)j * 384 + 3 * (size_t)f2);
    E.a = vrow[0]; E.b = vrow[1]; E.c = vrow[2];
}

__global__ __launch_bounds__(64, 5)
void node_kernel(const int* __restrict__ nbrs,
                 const float* __restrict__ r_ij,
                 const float* __restrict__ v_j,
                 const float* __restrict__ Wd,
                 const float* __restrict__ bd,
                 float* __restrict__ out) {
    int i   = blockIdx.x;
    int tid = threadIdx.x;          // 0..63
    int f2  = 2 * tid;              // first of this thread's feature pair
    int start = g_off[i];
    int end   = g_off[i + 1];

    // Wd column-pairs in registers (reused over ~32 edges): 60 f32x2 values
    ull wd0[NRBF], wd1[NRBF], wd2[NRBF];
    #pragma unroll
    for (int k = 0; k < NRBF; ++k) {
        const float* wrow = Wd + (size_t)k * 384;
        wd0[k] = *(const ull*)(wrow + f2);
        wd1[k] = *(const ull*)(wrow + 128 + f2);
        wd2[k] = *(const ull*)(wrow + 256 + f2);
    }
    ull bd0 = *(const ull*)(bd + f2);
    ull bd1 = *(const ull*)(bd + 128 + f2);
    ull bd2 = *(const ull*)(bd + 256 + f2);

    ull acc_s = 0ull, av0 = 0ull, av1 = 0ull, av2 = 0ull;  // 0.0f pairs

    __shared__ ull   s_rbf2[CHUNK][NRBF];  // sin(k*theta)*env/d, duplicated (r,r)
    __shared__ float s_unit[CHUNK][4];
    __shared__ float s_env[CHUNK];
    __shared__ int   s_j[CHUNK];

    for (int base = start; base < end; base += CHUNK) {
        int n = min(CHUNK, end - base);
        __syncthreads();  // protect smem from previous iteration's readers

        if (tid < n) {
            int e = g_perm[base + tid];
            s_j[tid] = nbrs[2 * e + 1];
            const float* rp = r_ij + 3 * (size_t)e;
            float x = rp[0], y = rp[1], z = rp[2];
            float d = sqrtf(fmaf(x, x, fmaf(y, y, fmaf(z, z, 3e-15f))));
            float invd = 1.f / d;
            s_unit[tid][0] = x * invd;
            s_unit[tid][1] = y * invd;
            s_unit[tid][2] = z * invd;
            // one accurate sincos; envelope reuses cos; rbf via Chebyshev recurrence
            float theta = d * (PI_F / CUTOFF);
            float st, ct;
            sincosf(theta, &st, &ct);
            float env = (d < CUTOFF) ? 0.5f * (ct + 1.f) : 0.f;
            s_env[tid] = env;
            float sc = env * invd;
            float c2  = 2.f * ct;
            float skm = 0.f;   // sin(0*theta)
            float sk  = st;    // sin(1*theta)
            #pragma unroll
            for (int k = 0; k < NRBF; ++k) {
                float r = sk * sc;
                s_rbf2[tid][k] = pack2(r, r);
                float nx = fmaf(c2, sk, -skm);
                skm = sk; sk = nx;
            }
        }
        __syncthreads();

        // prefetch edge 0's gathers
        EdgeRegs E, En;
        load_edge(En, s_j[0], f2, v_j);

        for (int t = 0; t < n; ++t) {
            E = En;
            if (t + 1 < n) load_edge(En, s_j[t + 1], f2, v_j);  // prefetch next

            float env = s_env[t];
            ull ep  = pack2(env, env);
            ull ws0 = mul2(bd0, ep);
            ull ws1 = mul2(bd1, ep);
            ull ws2 = mul2(bd2, ep);
            #pragma unroll
            for (int k = 0; k < NRBF; ++k) {
                ull rr = s_rbf2[t][k];        // LDS.64 broadcast
                ws0 = fma2(rr, wd0[k], ws0);
                ws1 = fma2(rr, wd1[k], ws1);
                ws2 = fma2(rr, wd2[k], ws2);
            }

            float u0 = s_unit[t][0], u1 = s_unit[t][1], u2 = s_unit[t][2];
            ull u0p = pack2(u0, u0);
            ull u1p = pack2(u1, u1);
            ull u2p = pack2(u2, u2);

            // v components for features (2t, 2t+1): a=(v0x,v0y) b=(v0z,v1x) c=(v1y,v1z)
            ull vx = pack2(E.a.x, E.b.y);
            ull vy = pack2(E.a.y, E.c.x);
            ull vz = pack2(E.b.x, E.c.y);

            ull i0 = mul2(E.p0, ws0);
            ull i2 = mul2(E.p2, ws2);
            acc_s = fma2(E.p1, ws1, acc_s);
            av0 = fma2(i0, vx, av0); av0 = fma2(i2, u0p, av0);
            av1 = fma2(i0, vy, av1); av1 = fma2(i2, u1p, av1);
            av2 = fma2(i0, vz, av2); av2 = fma2(i2, u2p, av2);
        }
    }

    // outputs: delta_s [N,128] then delta_v [N,128,3]
    float slo, shi;
    unpack2(acc_s, slo, shi);
    out[(size_t)i * FEAT + f2]     = slo;
    out[(size_t)i * FEAT + f2 + 1] = shi;

    float a0l, a0h, a1l, a1h, a2l, a2h;
    unpack2(av0, a0l, a0h);
    unpack2(av1, a1l, a1h);
    unpack2(av2, a2l, a2h);
    float* vout = out + (size_t)N_NODES * FEAT + ((size_t)i * FEAT + f2) * 3;
    vout[0] = a0l; vout[1] = a1l; vout[2] = a2l;
    vout[3] = a0h; vout[4] = a1h; vout[5] = a2h;
}

// ---------------- launch ------------------------------------------------------
extern "C" void kernel_launch(void* const* d_in, const int* in_sizes, int n_in,
                              void* d_out, int out_size) {
    const float* s_j  = (const float*)d_in[0];
    const float* v_j  = (const float*)d_in[1];
    const float* r_ij = (const float*)d_in[2];
    const int*   nbrs = (const int*)d_in[3];     // int32 (JAX x64 disabled)
    const float* W1   = (const float*)d_in[4];
    const float* b1   = (const float*)d_in[5];
    const float* W2   = (const float*)d_in[6];
    const float* b2   = (const float*)d_in[7];
    const float* Wd   = (const float*)d_in[8];
    const float* bd   = (const float*)d_in[9];
    float* out = (float*)d_out;

    zero_counts_kernel<<<(N_NODES + 255) / 256, 256>>>();
    hist_kernel<<<N_EDGES / 256, 256>>>(nbrs);
    scan_kernel<<<1, 1024>>>();
    scatter_kernel<<<N_EDGES / 256, 256>>>(nbrs);

    gemm1_kernel<<<N_NODES / 16, 128>>>(s_j, W1, b1);
    gemm2_kernel<<<N_NODES / 16, 128>>>(W2, b2);

    node_kernel<<<N_NODES, 64>>>(nbrs, r_ij, v_j, Wd, bd, out);
}

// round 6
// speedup vs baseline: 1.1403x; 1.1403x over previous
#include <cuda_runtime.h>
#include <cuda_bf16.h>
#include <math.h>

#define N_NODES 20000
#define N_EDGES 640000
#define FEAT    128
#define NRBF    20
#define PI_F    3.14159265358979f
#define CUTOFF  5.0f
#define CHUNK   32

typedef unsigned long long ull;

// ---------------- f32x2 packed-math helpers (Blackwell FFMA2 path) -----------
__device__ __forceinline__ ull pack2(float lo, float hi) {
    ull r; asm("mov.b64 %0, {%1, %2};" : "=l"(r) : "f"(lo), "f"(hi)); return r;
}
__device__ __forceinline__ void unpack2(ull v, float& lo, float& hi) {
    asm("mov.b64 {%0, %1}, %2;" : "=f"(lo), "=f"(hi) : "l"(v));
}
__device__ __forceinline__ ull fma2(ull a, ull b, ull c) {
    ull d; asm("fma.rn.f32x2 %0, %1, %2, %3;" : "=l"(d) : "l"(a), "l"(b), "l"(c)); return d;
}
__device__ __forceinline__ ull mul2(ull a, ull b) {
    ull d; asm("mul.rn.f32x2 %0, %1, %2;" : "=l"(d) : "l"(a), "l"(b)); return d;
}
__device__ __forceinline__ void pf_l1(const void* p) {
    asm volatile("prefetch.global.L1 [%0];" :: "l"(p));
}

// ---------------- scratch (static device allocations; no cudaMalloc) ----------
__device__ int   g_count[N_NODES];
__device__ int   g_off[N_NODES + 1];
__device__ int   g_cursor[N_NODES];
__device__ int   g_perm[N_EDGES];
__device__ float g_h[N_NODES * FEAT];          // 10.24 MB
__device__ float g_phi[N_NODES * 3 * FEAT];    // 30.72 MB

// ---------------- counting sort of edges by destination node ------------------
// nbrs is int32 [N_EDGES, 2]: nbrs[2e] = dest node i, nbrs[2e+1] = src node j
__global__ void zero_counts_kernel() {
    int i = blockIdx.x * blockDim.x + threadIdx.x;
    if (i < N_NODES) g_count[i] = 0;
}

__global__ void hist_kernel(const int* __restrict__ nbrs) {
    int e = blockIdx.x * blockDim.x + threadIdx.x;
    if (e < N_EDGES) {
        int i = nbrs[2 * e];
        atomicAdd(&g_count[i], 1);
    }
}

// single-block scan: 1024 threads x strip of 20 -> covers 20480 >= 20000
__global__ void scan_kernel() {
    const int STRIP = 20;
    int t = threadIdx.x;
    int base = t * STRIP;
    int local[STRIP];
    int s = 0;
    #pragma unroll
    for (int u = 0; u < STRIP; ++u) {
        int idx = base + u;
        int c = (idx < N_NODES) ? g_count[idx] : 0;
        local[u] = s;       // exclusive within strip
        s += c;
    }
    __shared__ int sums[1024];
    sums[t] = s;
    __syncthreads();
    for (int off = 1; off < 1024; off <<= 1) {
        int v = (t >= off) ? sums[t - off] : 0;
        __syncthreads();
        sums[t] += v;
        __syncthreads();
    }
    int pre = (t > 0) ? sums[t - 1] : 0;
    #pragma unroll
    for (int u = 0; u < STRIP; ++u) {
        int idx = base + u;
        if (idx < N_NODES) {
            int o = pre + local[u];
            g_off[idx]    = o;
            g_cursor[idx] = o;
        }
    }
    if (t == 1023) g_off[N_NODES] = sums[1023];
}

__global__ void scatter_kernel(const int* __restrict__ nbrs) {
    int e = blockIdx.x * blockDim.x + threadIdx.x;
    if (e < N_EDGES) {
        int i = nbrs[2 * e];
        int pos = atomicAdd(&g_cursor[i], 1);
        g_perm[pos] = e;
    }
}

// ---------------- node-feature GEMMs ------------------------------------------
// h = silu(s @ W1 + b1)   [20000,128] @ [128,128]
__global__ __launch_bounds__(128, 4)
void gemm1_kernel(const float* __restrict__ S, const float* __restrict__ W1,
                  const float* __restrict__ b1) {
    __shared__ float As[16][FEAT];
    int row0 = blockIdx.x * 16;
    int tid = threadIdx.x;
    #pragma unroll
    for (int r = 0; r < 16; ++r)
        As[r][tid] = S[(size_t)(row0 + r) * FEAT + tid];
    __syncthreads();

    float acc[16];
    #pragma unroll
    for (int r = 0; r < 16; ++r) acc[r] = 0.f;

    int c = tid;
    #pragma unroll 4
    for (int k = 0; k < FEAT; ++k) {
        float b = W1[k * FEAT + c];
        #pragma unroll
        for (int r = 0; r < 16; ++r) acc[r] = fmaf(As[r][k], b, acc[r]);
    }
    float bias = b1[c];
    #pragma unroll
    for (int r = 0; r < 16; ++r) {
        float x = acc[r] + bias;
        g_h[(size_t)(row0 + r) * FEAT + c] = x / (1.f + expf(-x));  // silu
    }
}

// phi = h @ W2 + b2   [20000,128] @ [128,384]
__global__ __launch_bounds__(128, 4)
void gemm2_kernel(const float* __restrict__ W2, const float* __restrict__ b2) {
    __shared__ float Hs[16][FEAT];
    int row0 = blockIdx.x * 16;
    int tid = threadIdx.x;
    #pragma unroll
    for (int r = 0; r < 16; ++r)
        Hs[r][tid] = g_h[(size_t)(row0 + r) * FEAT + tid];
    __syncthreads();

    float a0[16], a1[16], a2[16];
    #pragma unroll
    for (int r = 0; r < 16; ++r) { a0[r] = 0.f; a1[r] = 0.f; a2[r] = 0.f; }

    int c = tid;
    #pragma unroll 2
    for (int k = 0; k < FEAT; ++k) {
        const float* wrow = W2 + (size_t)k * 384;
        float b0 = wrow[c];
        float b1v = wrow[128 + c];
        float b2v = wrow[256 + c];
        #pragma unroll
        for (int r = 0; r < 16; ++r) {
            float h = Hs[r][k];
            a0[r] = fmaf(h, b0, a0[r]);
            a1[r] = fmaf(h, b1v, a1[r]);
            a2[r] = fmaf(h, b2v, a2[r]);
        }
    }
    float bb0 = b2[c], bb1 = b2[128 + c], bb2 = b2[256 + c];
    #pragma unroll
    for (int r = 0; r < 16; ++r) {
        float* prow = g_phi + (size_t)(row0 + r) * 384;
        prow[c]       = a0[r] + bb0;
        prow[128 + c] = a1[r] + bb1;
        prow[256 + c] = a2[r] + bb2;
    }
}

// ---------------- per-node message + aggregation (f32x2 packed) ---------------
// One CTA (64 threads) per destination node i.
// Thread t owns feature columns (2t, 2t+1) of each of the 3 splits.
struct EdgeRegs { ull p0, p1, p2; float2 a, b, c; };

__device__ __forceinline__ void load_edge(EdgeRegs& E, int j, int f2,
                                          const float* __restrict__ v_j) {
    const float* prow = g_phi + (size_t)j * 384;
    E.p0 = *(const ull*)(prow + f2);
    E.p1 = *(const ull*)(prow + 128 + f2);
    E.p2 = *(const ull*)(prow + 256 + f2);
    const float2* vrow = (const float2*)(v_j + (size_t)j * 384 + 3 * (size_t)f2);
    E.a = vrow[0]; E.b = vrow[1]; E.c = vrow[2];
}

__global__ __launch_bounds__(64, 5)
void node_kernel(const int* __restrict__ nbrs,
                 const float* __restrict__ r_ij,
                 const float* __restrict__ v_j,
                 const float* __restrict__ Wd,
                 const float* __restrict__ bd,
                 float* __restrict__ out) {
    int i   = blockIdx.x;
    int tid = threadIdx.x;          // 0..63
    int f2  = 2 * tid;              // first of this thread's feature pair
    int start = g_off[i];
    int end   = g_off[i + 1];

    // Wd column-pairs in registers; slot 20 = bd (paired with env as 21st rbf)
    ull wd0[NRBF + 1], wd1[NRBF + 1], wd2[NRBF + 1];
    #pragma unroll
    for (int k = 0; k < NRBF; ++k) {
        const float* wrow = Wd + (size_t)k * 384;
        wd0[k] = *(const ull*)(wrow + f2);
        wd1[k] = *(const ull*)(wrow + 128 + f2);
        wd2[k] = *(const ull*)(wrow + 256 + f2);
    }
    wd0[NRBF] = *(const ull*)(bd + f2);
    wd1[NRBF] = *(const ull*)(bd + 128 + f2);
    wd2[NRBF] = *(const ull*)(bd + 256 + f2);

    ull acc_s = 0ull, av0 = 0ull, av1 = 0ull, av2 = 0ull;  // 0.0f pairs

    __shared__ ull s_rbf2[CHUNK][NRBF + 1];  // [k<20]: sin(k*th)*env/d dup; [20]: env dup
    __shared__ ull s_u[CHUNK][3];            // unit vector components, duplicated
    __shared__ int s_j[CHUNK];

    for (int base = start; base < end; base += CHUNK) {
        int n = min(CHUNK, end - base);
        __syncthreads();  // protect smem from previous iteration's readers

        if (tid < n) {
            int e = g_perm[base + tid];
            s_j[tid] = nbrs[2 * e + 1];
            const float* rp = r_ij + 3 * (size_t)e;
            float x = rp[0], y = rp[1], z = rp[2];
            float d = sqrtf(fmaf(x, x, fmaf(y, y, fmaf(z, z, 3e-15f))));
            float invd = 1.f / d;
            s_u[tid][0] = pack2(x * invd, x * invd);
            s_u[tid][1] = pack2(y * invd, y * invd);
            s_u[tid][2] = pack2(z * invd, z * invd);
            // one fast sincos; envelope reuses cos; rbf via Chebyshev recurrence.
            // For contributing edges d < CUTOFF => theta < pi (MUFU-accurate range);
            // d >= CUTOFF edges are exactly zeroed by env.
            float theta = d * (PI_F / CUTOFF);
            float st, ct;
            __sincosf(theta, &st, &ct);
            float env = (d < CUTOFF) ? 0.5f * (ct + 1.f) : 0.f;
            s_rbf2[tid][NRBF] = pack2(env, env);
            float sc = env * invd;
            float c2  = 2.f * ct;
            float skm = 0.f;   // sin(0*theta)
            float sk  = st;    // sin(1*theta)
            #pragma unroll
            for (int k = 0; k < NRBF; ++k) {
                float r = sk * sc;
                s_rbf2[tid][k] = pack2(r, r);
                float nx = fmaf(c2, sk, -skm);
                skm = sk; sk = nx;
            }
        }
        __syncthreads();

        // register prefetch depth 1
        EdgeRegs E, En;
        load_edge(En, s_j[0], f2, v_j);

        for (int t = 0; t < n; ++t) {
            E = En;
            if (t + 1 < n) load_edge(En, s_j[t + 1], f2, v_j);  // reg prefetch t+1

            // L1 prefetch depth 2 (no register cost; covers L2 latency)
            {
                int jp = s_j[min(t + 2, n - 1)];
                const float* pp = g_phi + (size_t)jp * 384;
                pf_l1(pp + f2);
                pf_l1(pp + 128 + f2);
                pf_l1(pp + 256 + f2);
                pf_l1(v_j + (size_t)jp * 384 + 3 * (size_t)f2);
            }

            ull ws0 = 0ull, ws1 = 0ull, ws2 = 0ull;
            #pragma unroll
            for (int k = 0; k <= NRBF; ++k) {
                ull rr = s_rbf2[t][k];        // LDS.64 broadcast
                ws0 = fma2(rr, wd0[k], ws0);
                ws1 = fma2(rr, wd1[k], ws1);
                ws2 = fma2(rr, wd2[k], ws2);
            }

            ull u0p = s_u[t][0];
            ull u1p = s_u[t][1];
            ull u2p = s_u[t][2];

            // v components for features (2t, 2t+1): a=(v0x,v0y) b=(v0z,v1x) c=(v1y,v1z)
            ull vx = pack2(E.a.x, E.b.y);
            ull vy = pack2(E.a.y, E.c.x);
            ull vz = pack2(E.b.x, E.c.y);

            ull i0 = mul2(E.p0, ws0);
            ull i2 = mul2(E.p2, ws2);
            acc_s = fma2(E.p1, ws1, acc_s);
            av0 = fma2(i0, vx, av0); av0 = fma2(i2, u0p, av0);
            av1 = fma2(i0, vy, av1); av1 = fma2(i2, u1p, av1);
            av2 = fma2(i0, vz, av2); av2 = fma2(i2, u2p, av2);
        }
    }

    // outputs: delta_s [N,128] then delta_v [N,128,3]
    float slo, shi;
    unpack2(acc_s, slo, shi);
    out[(size_t)i * FEAT + f2]     = slo;
    out[(size_t)i * FEAT + f2 + 1] = shi;

    float a0l, a0h, a1l, a1h, a2l, a2h;
    unpack2(av0, a0l, a0h);
    unpack2(av1, a1l, a1h);
    unpack2(av2, a2l, a2h);
    float* vout = out + (size_t)N_NODES * FEAT + ((size_t)i * FEAT + f2) * 3;
    vout[0] = a0l; vout[1] = a1l; vout[2] = a2l;
    vout[3] = a0h; vout[4] = a1h; vout[5] = a2h;
}

// ---------------- launch ------------------------------------------------------
extern "C" void kernel_launch(void* const* d_in, const int* in_sizes, int n_in,
                              void* d_out, int out_size) {
    const float* s_j  = (const float*)d_in[0];
    const float* v_j  = (const float*)d_in[1];
    const float* r_ij = (const float*)d_in[2];
    const int*   nbrs = (const int*)d_in[3];     // int32 (JAX x64 disabled)
    const float* W1   = (const float*)d_in[4];
    const float* b1   = (const float*)d_in[5];
    const float* W2   = (const float*)d_in[6];
    const float* b2   = (const float*)d_in[7];
    const float* Wd   = (const float*)d_in[8];
    const float* bd   = (const float*)d_in[9];
    float* out = (float*)d_out;

    zero_counts_kernel<<<(N_NODES + 255) / 256, 256>>>();
    hist_kernel<<<N_EDGES / 256, 256>>>(nbrs);
    scan_kernel<<<1, 1024>>>();
    scatter_kernel<<<N_EDGES / 256, 256>>>(nbrs);

    gemm1_kernel<<<N_NODES / 16, 128>>>(s_j, W1, b1);
    gemm2_kernel<<<N_NODES / 16, 128>>>(W2, b2);

    node_kernel<<<N_NODES, 64>>>(nbrs, r_ij, v_j, Wd, bd, out);
}

// round 7
// speedup vs baseline: 1.1952x; 1.0482x over previous
#include <cuda_runtime.h>
#include <cuda_bf16.h>
#include <math.h>

#define N_NODES 20000
#define N_EDGES 640000
#define FEAT    128
#define NRBF    20
#define PI_F    3.14159265358979f
#define CUTOFF  5.0f
#define CHUNK   32
#define PFD     6      // L1 prefetch depth (edges)

typedef unsigned long long ull;

// ---------------- f32x2 packed-math helpers (Blackwell FFMA2 path) -----------
__device__ __forceinline__ ull pack2(float lo, float hi) {
    ull r; asm("mov.b64 %0, {%1, %2};" : "=l"(r) : "f"(lo), "f"(hi)); return r;
}
__device__ __forceinline__ void unpack2(ull v, float& lo, float& hi) {
    asm("mov.b64 {%0, %1}, %2;" : "=f"(lo), "=f"(hi) : "l"(v));
}
__device__ __forceinline__ ull fma2(ull a, ull b, ull c) {
    ull d; asm("fma.rn.f32x2 %0, %1, %2, %3;" : "=l"(d) : "l"(a), "l"(b), "l"(c)); return d;
}
__device__ __forceinline__ ull mul2(ull a, ull b) {
    ull d; asm("mul.rn.f32x2 %0, %1, %2;" : "=l"(d) : "l"(a), "l"(b)); return d;
}
__device__ __forceinline__ void pf_l1(const void* p) {
    asm volatile("prefetch.global.L1 [%0];" :: "l"(p));
}

// ---------------- scratch (static device allocations; no cudaMalloc) ----------
__device__ int   g_count[N_NODES];
__device__ int   g_off[N_NODES + 1];
__device__ int   g_cursor[N_NODES];
__device__ int   g_perm[N_EDGES];
__device__ float g_phi[N_NODES * 3 * FEAT];    // 30.72 MB

// ---------------- counting sort of edges by destination node ------------------
// nbrs is int32 [N_EDGES, 2]: nbrs[2e] = dest node i, nbrs[2e+1] = src node j
__global__ void zero_counts_kernel() {
    int i = blockIdx.x * blockDim.x + threadIdx.x;
    if (i < N_NODES) g_count[i] = 0;
}

__global__ void hist_kernel(const int* __restrict__ nbrs) {
    int e = blockIdx.x * blockDim.x + threadIdx.x;
    if (e < N_EDGES) {
        int i = nbrs[2 * e];
        atomicAdd(&g_count[i], 1);
    }
}

// single-block scan: 1024 threads x strip of 20 -> covers 20480 >= 20000
__global__ void scan_kernel() {
    const int STRIP = 20;
    int t = threadIdx.x;
    int base = t * STRIP;
    int local[STRIP];
    int s = 0;
    #pragma unroll
    for (int u = 0; u < STRIP; ++u) {
        int idx = base + u;
        int c = (idx < N_NODES) ? g_count[idx] : 0;
        local[u] = s;       // exclusive within strip
        s += c;
    }
    __shared__ int sums[1024];
    sums[t] = s;
    __syncthreads();
    for (int off = 1; off < 1024; off <<= 1) {
        int v = (t >= off) ? sums[t - off] : 0;
        __syncthreads();
        sums[t] += v;
        __syncthreads();
    }
    int pre = (t > 0) ? sums[t - 1] : 0;
    #pragma unroll
    for (int u = 0; u < STRIP; ++u) {
        int idx = base + u;
        if (idx < N_NODES) {
            int o = pre + local[u];
            g_off[idx]    = o;
            g_cursor[idx] = o;
        }
    }
    if (t == 1023) g_off[N_NODES] = sums[1023];
}

__global__ void scatter_kernel(const int* __restrict__ nbrs) {
    int e = blockIdx.x * blockDim.x + threadIdx.x;
    if (e < N_EDGES) {
        int i = nbrs[2 * e];
        int pos = atomicAdd(&g_cursor[i], 1);
        g_perm[pos] = e;
    }
}

// ---------------- fused node-feature MLP --------------------------------------
// phi = silu(s @ W1 + b1) @ W2 + b2, h kept in smem (no global round-trip)
__global__ __launch_bounds__(128, 4)
void gemm_fused_kernel(const float* __restrict__ S,
                       const float* __restrict__ W1, const float* __restrict__ b1,
                       const float* __restrict__ W2, const float* __restrict__ b2) {
    __shared__ float As[16][FEAT];
    __shared__ float Hs[16][FEAT];
    int row0 = blockIdx.x * 16;
    int tid = threadIdx.x;
    #pragma unroll
    for (int r = 0; r < 16; ++r)
        As[r][tid] = S[(size_t)(row0 + r) * FEAT + tid];
    __syncthreads();

    {
        float acc[16];
        #pragma unroll
        for (int r = 0; r < 16; ++r) acc[r] = 0.f;
        #pragma unroll 4
        for (int k = 0; k < FEAT; ++k) {
            float b = W1[k * FEAT + tid];
            #pragma unroll
            for (int r = 0; r < 16; ++r) acc[r] = fmaf(As[r][k], b, acc[r]);
        }
        float bias = b1[tid];
        #pragma unroll
        for (int r = 0; r < 16; ++r) {
            float x = acc[r] + bias;
            Hs[r][tid] = x / (1.f + expf(-x));   // silu
        }
    }
    __syncthreads();

    float a0[16], a1[16], a2[16];
    #pragma unroll
    for (int r = 0; r < 16; ++r) { a0[r] = 0.f; a1[r] = 0.f; a2[r] = 0.f; }

    #pragma unroll 2
    for (int k = 0; k < FEAT; ++k) {
        const float* wrow = W2 + (size_t)k * 384;
        float b0 = wrow[tid];
        float b1v = wrow[128 + tid];
        float b2v = wrow[256 + tid];
        #pragma unroll
        for (int r = 0; r < 16; ++r) {
            float h = Hs[r][k];
            a0[r] = fmaf(h, b0, a0[r]);
            a1[r] = fmaf(h, b1v, a1[r]);
            a2[r] = fmaf(h, b2v, a2[r]);
        }
    }
    float bb0 = b2[tid], bb1 = b2[128 + tid], bb2 = b2[256 + tid];
    #pragma unroll
    for (int r = 0; r < 16; ++r) {
        float* prow = g_phi + (size_t)(row0 + r) * 384;
        prow[tid]       = a0[r] + bb0;
        prow[128 + tid] = a1[r] + bb1;
        prow[256 + tid] = a2[r] + bb2;
    }
}

// ---------------- per-node message + aggregation (f32x2 packed) ---------------
// One CTA (64 threads) per destination node i.
// Thread t owns feature columns (2t, 2t+1) of each of the 3 splits.
__global__ __launch_bounds__(64, 5)
void node_kernel(const int* __restrict__ nbrs,
                 const float* __restrict__ r_ij,
                 const float* __restrict__ v_j,
                 const float* __restrict__ Wd,
                 const float* __restrict__ bd,
                 float* __restrict__ out) {
    int i   = blockIdx.x;
    int tid = threadIdx.x;          // 0..63
    int f2  = 2 * tid;              // first of this thread's feature pair
    int start = g_off[i];
    int end   = g_off[i + 1];

    // Wd column-pairs in registers; slot 20 = bd (paired with env as 21st rbf)
    ull wd0[NRBF + 1], wd1[NRBF + 1], wd2[NRBF + 1];
    #pragma unroll
    for (int k = 0; k < NRBF; ++k) {
        const float* wrow = Wd + (size_t)k * 384;
        wd0[k] = *(const ull*)(wrow + f2);
        wd1[k] = *(const ull*)(wrow + 128 + f2);
        wd2[k] = *(const ull*)(wrow + 256 + f2);
    }
    wd0[NRBF] = *(const ull*)(bd + f2);
    wd1[NRBF] = *(const ull*)(bd + 128 + f2);
    wd2[NRBF] = *(const ull*)(bd + 256 + f2);

    ull acc_s = 0ull, av0 = 0ull, av1 = 0ull, av2 = 0ull;  // 0.0f pairs

    __shared__ ull s_rbf2[CHUNK][NRBF + 1];  // [k<20]: sin(k*th)*env/d dup; [20]: env dup
    __shared__ ull s_u[CHUNK][3];            // unit vector components, duplicated
    __shared__ int s_j[CHUNK];

    for (int base = start; base < end; base += CHUNK) {
        int n = min(CHUNK, end - base);
        __syncthreads();  // protect smem from previous iteration's readers

        if (tid < n) {
            int e = g_perm[base + tid];
            s_j[tid] = nbrs[2 * e + 1];
            const float* rp = r_ij + 3 * (size_t)e;
            float x = rp[0], y = rp[1], z = rp[2];
            float d = sqrtf(fmaf(x, x, fmaf(y, y, fmaf(z, z, 3e-15f))));
            float invd = 1.f / d;
            s_u[tid][0] = pack2(x * invd, x * invd);
            s_u[tid][1] = pack2(y * invd, y * invd);
            s_u[tid][2] = pack2(z * invd, z * invd);
            // one fast sincos; envelope reuses cos; rbf via Chebyshev recurrence.
            // Contributing edges have theta < pi (MUFU-accurate); d >= CUTOFF zeroed by env.
            float theta = d * (PI_F / CUTOFF);
            float st, ct;
            __sincosf(theta, &st, &ct);
            float env = (d < CUTOFF) ? 0.5f * (ct + 1.f) : 0.f;
            s_rbf2[tid][NRBF] = pack2(env, env);
            float sc = env * invd;
            float c2  = 2.f * ct;
            float skm = 0.f;   // sin(0*theta)
            float sk  = st;    // sin(1*theta)
            #pragma unroll
            for (int k = 0; k < NRBF; ++k) {
                float r = sk * sc;
                s_rbf2[tid][k] = pack2(r, r);
                float nx = fmaf(c2, sk, -skm);
                skm = sk; sk = nx;
            }
        }
        __syncthreads();

        // warm-up: prefetch first PFD edges' rows into L1
        int npf = min(PFD, n);
        for (int t0 = 0; t0 < npf; ++t0) {
            int jp = s_j[t0];
            const float* pp = g_phi + (size_t)jp * 384;
            pf_l1(pp + f2);
            pf_l1(pp + 128 + f2);
            pf_l1(pp + 256 + f2);
            pf_l1(v_j + (size_t)jp * 384 + 3 * (size_t)f2);
        }

        for (int t = 0; t < n; ++t) {
            // steady-state L1 prefetch, depth PFD (no register cost)
            if (t + PFD < n) {
                int jp = s_j[t + PFD];
                const float* pp = g_phi + (size_t)jp * 384;
                pf_l1(pp + f2);
                pf_l1(pp + 128 + f2);
                pf_l1(pp + 256 + f2);
                pf_l1(v_j + (size_t)jp * 384 + 3 * (size_t)f2);
            }

            int j = s_j[t];
            const float* prow = g_phi + (size_t)j * 384;
            ull p0 = *(const ull*)(prow + f2);
            ull p1 = *(const ull*)(prow + 128 + f2);
            ull p2 = *(const ull*)(prow + 256 + f2);
            const float2* vrow = (const float2*)(v_j + (size_t)j * 384 + 3 * (size_t)f2);
            float2 va = vrow[0], vb = vrow[1], vc = vrow[2];

            ull ws0 = 0ull, ws1 = 0ull, ws2 = 0ull;
            #pragma unroll
            for (int k = 0; k <= NRBF; ++k) {
                ull rr = s_rbf2[t][k];        // LDS.64 broadcast
                ws0 = fma2(rr, wd0[k], ws0);
                ws1 = fma2(rr, wd1[k], ws1);
                ws2 = fma2(rr, wd2[k], ws2);
            }

            // v components for features (2t, 2t+1): va=(v0x,v0y) vb=(v0z,v1x) vc=(v1y,v1z)
            ull vx = pack2(va.x, vb.y);
            ull vy = pack2(va.y, vc.x);
            ull vz = pack2(vb.x, vc.y);

            ull i0 = mul2(p0, ws0);
            ull i2 = mul2(p2, ws2);
            acc_s = fma2(p1, ws1, acc_s);
            av0 = fma2(i0, vx, av0); av0 = fma2(i2, s_u[t][0], av0);
            av1 = fma2(i0, vy, av1); av1 = fma2(i2, s_u[t][1], av1);
            av2 = fma2(i0, vz, av2); av2 = fma2(i2, s_u[t][2], av2);
        }
    }

    // outputs: delta_s [N,128] then delta_v [N,128,3]
    float slo, shi;
    unpack2(acc_s, slo, shi);
    out[(size_t)i * FEAT + f2]     = slo;
    out[(size_t)i * FEAT + f2 + 1] = shi;

    float a0l, a0h, a1l, a1h, a2l, a2h;
    unpack2(av0, a0l, a0h);
    unpack2(av1, a1l, a1h);
    unpack2(av2, a2l, a2h);
    float* vout = out + (size_t)N_NODES * FEAT + ((size_t)i * FEAT + f2) * 3;
    vout[0] = a0l; vout[1] = a1l; vout[2] = a2l;
    vout[3] = a0h; vout[4] = a1h; vout[5] = a2h;
}

// ---------------- launch ------------------------------------------------------
extern "C" void kernel_launch(void* const* d_in, const int* in_sizes, int n_in,
                              void* d_out, int out_size) {
    const float* s_j  = (const float*)d_in[0];
    const float* v_j  = (const float*)d_in[1];
    const float* r_ij = (const float*)d_in[2];
    const int*   nbrs = (const int*)d_in[3];     // int32 (JAX x64 disabled)
    const float* W1   = (const float*)d_in[4];
    const float* b1   = (const float*)d_in[5];
    const float* W2   = (const float*)d_in[6];
    const float* b2   = (const float*)d_in[7];
    const float* Wd   = (const float*)d_in[8];
    const float* bd   = (const float*)d_in[9];
    float* out = (float*)d_out;

    zero_counts_kernel<<<(N_NODES + 255) / 256, 256>>>();
    hist_kernel<<<N_EDGES / 256, 256>>>(nbrs);
    scan_kernel<<<1, 1024>>>();
    scatter_kernel<<<N_EDGES / 256, 256>>>(nbrs);

    gemm_fused_kernel<<<N_NODES / 16, 128>>>(s_j, W1, b1, W2, b2);

    node_kernel<<<N_NODES, 64>>>(nbrs, r_ij, v_j, Wd, bd, out);
}